// round 15
// baseline (speedup 1.0000x reference)
#include <cuda_runtime.h>
#include <cuda_bf16.h>
#include <cstdint>

// ---------------- problem constants ----------------
#define BN      4096
#define KN      20
#define D_EMB   128
#define D_FEAT  172
#define D_TIME  100
#define KTOT    444              // node 172 | edge 172 | time 100
#define GROWS   4                // batch rows per block
#define XS_ST   12               // xs k-stride: 48B per k -> 16B-aligned row quads
#define TPB     128              // 32 threads per row (validated ratio)
#define TASKS_PER_ROW 224        // 43 node-f4 | 43 edge-f4 | 32 mem-f4 | 100 cos | 6 pad
#define NTASKS  (GROWS * TASKS_PER_ROW)   // 896

typedef unsigned long long ull;

// ---------------- accurate cos for large fp32 args (validated) ----------------
__device__ __forceinline__ float cos_cw(float x) {
    const float TWO_OVER_PI = 0.63661977236758134f;
    const float P1 = 1.57079625129699707031e+00f;
    const float P2 = 7.54978941586159375e-08f;
    const float P3 = 5.39030252995776477e-15f;
    float n = rintf(x * TWO_OVER_PI);
    float r = fmaf(n, -P1, x);
    r = fmaf(n, -P2, r);
    r = fmaf(n, -P3, r);
    int q = ((int)n) & 3;
    float r2 = r * r;
    float s = fmaf(r2, -1.98412698412698413e-4f, 8.33333333333333322e-3f);
    s = fmaf(r2, s, -1.66666666666666666e-1f);
    s = r * fmaf(r2, s, 1.0f);
    float c = fmaf(r2, 2.48015873015873016e-5f, -1.38888888888888889e-3f);
    c = fmaf(r2, c, 4.16666666666666666e-2f);
    c = fmaf(r2, c, -0.5f);
    c = fmaf(r2, c, 1.0f);
    float v = (q & 1) ? s : c;
    if ((q + 1) & 2) v = -v;
    return v;
}

// ---------------- f32x2 packed helpers ----------------
__device__ __forceinline__ ull dup2(float v) {
    ull r;
    asm("mov.b64 %0, {%1, %1};" : "=l"(r) : "f"(v));
    return r;
}
__device__ __forceinline__ void fma2(ull& d, ull a, ull b) {
    asm("fma.rn.f32x2 %0, %1, %2, %0;" : "+l"(d) : "l"(a), "l"(b));
}
__device__ __forceinline__ void unpack2(ull v, float& lo, float& hi) {
    asm("mov.b64 {%0, %1}, %2;" : "=f"(lo), "=f"(hi) : "l"(v));
}

// ---------------- fused gather + masked-mean + projection GEMM ----------------
// Block = 4 batch rows, 128 threads (32/row, validated). Grid 1024 -> 6.9 blocks/SM
// (wave imbalance 14% instead of 33% at grid 512). Phase 1: task-based float4
// gather-reduce into transposed xs + sbase. Phase 2: thread = one column x all
// 4 rows (2 f32x2 accs, one LDS.128 broadcast per k), W read once per column.
__global__ void __launch_bounds__(TPB) fused_kernel(
    const float* __restrict__ nf, const float* __restrict__ ef,
    const float* __restrict__ mem,
    const float* __restrict__ ts, const float* __restrict__ ets,
    const float* __restrict__ tw, const float* __restrict__ tb,
    const int* __restrict__ srcn, const int* __restrict__ nbr,
    const int* __restrict__ eidx,
    const float* __restrict__ W_node, const float* __restrict__ W_edge,
    const float* __restrict__ W_time,
    float* __restrict__ out)
{
    __shared__ __align__(16) float xs[KTOT * XS_ST];   // 21312 B (rows 0-3 of each quad used)
    __shared__ float sbase[GROWS * D_EMB];             // 2048 B memory terms
    __shared__ int   s_nbr[GROWS * KN];
    __shared__ int   s_eid[GROWS * KN];
    __shared__ float s_del[GROWS * KN];
    __shared__ float s_msk[GROWS * KN];
    __shared__ float s_inv[GROWS];
    __shared__ int   s_src[GROWS];

    const int t = threadIdx.x;
    const int m0 = blockIdx.x * GROWS;

    // ---- phase 0: metadata ----
    if (t < GROWS * KN) {                    // 80 threads
        const int row = t / KN;
        const int kk = t - row * KN;
        const int gb = m0 + row;
        const int nb = __ldg(&nbr[gb * KN + kk]);
        s_nbr[t] = nb;
        s_eid[t] = __ldg(&eidx[gb * KN + kk]);
        s_del[t] = __ldg(&ts[gb]) - __ldg(&ets[gb * KN + kk]);
        s_msk[t] = (nb != 0) ? 1.f : 0.f;
    }
    if (t >= 96 && t < 96 + GROWS) s_src[t - 96] = __ldg(&srcn[m0 + (t - 96)]);
    __syncthreads();
    if (t < GROWS) {
        float c = 0.f;
        #pragma unroll
        for (int k = 0; k < KN; k++) c += s_msk[t * KN + k];
        s_inv[t] = 1.f / fmaxf(c, 1.f);
    }
    __syncthreads();

    // ---- phase 1: task loop (gather/reduce into xs + sbase) — validated ----
    for (int ti = t; ti < NTASKS; ti += TPB) {
        const int row = ti / TASKS_PER_ROW;
        const int tt = ti - row * TASKS_PER_ROW;
        const float inv = s_inv[row];
        const float* mk = &s_msk[row * KN];

        if (tt < 118) {
            const float* bp;
            int stride, colo, xoff;
            const int* rs;
            bool add_src, to_base = false;
            if (tt < 43)      { bp = nf;  stride = D_FEAT; colo = 4 * tt;        rs = &s_nbr[row * KN]; xoff = 0;      add_src = true; }
            else if (tt < 86) { bp = ef;  stride = D_FEAT; colo = 4 * (tt - 43); rs = &s_eid[row * KN]; xoff = D_FEAT; add_src = false; }
            else              { bp = mem; stride = D_EMB;  colo = 4 * (tt - 86); rs = &s_nbr[row * KN]; xoff = 0;      add_src = true; to_base = true; }

            float4 acc = make_float4(0.f, 0.f, 0.f, 0.f);
            #pragma unroll
            for (int k = 0; k < KN; k++) {
                const float m = mk[k];
                const float4 v = __ldg((const float4*)(bp + (size_t)rs[k] * stride + colo));
                acc.x = fmaf(m, v.x, acc.x);
                acc.y = fmaf(m, v.y, acc.y);
                acc.z = fmaf(m, v.z, acc.z);
                acc.w = fmaf(m, v.w, acc.w);
            }
            acc.x *= inv; acc.y *= inv; acc.z *= inv; acc.w *= inv;
            if (add_src) {
                const float4 sv = __ldg((const float4*)(bp + (size_t)s_src[row] * stride + colo));
                acc.x += sv.x; acc.y += sv.y; acc.z += sv.z; acc.w += sv.w;
            }
            if (to_base) {
                *(float4*)&sbase[row * D_EMB + colo] = acc;
            } else {
                const int c = xoff + colo;
                xs[(c + 0) * XS_ST + row] = acc.x;
                xs[(c + 1) * XS_ST + row] = acc.y;
                xs[(c + 2) * XS_ST + row] = acc.z;
                xs[(c + 3) * XS_ST + row] = acc.w;
            }
        } else if (tt < 218) {
            const int j = tt - 118;
            const float wj = __ldg(&tw[j]);
            const float bj = __ldg(&tb[j]);
            const float* dl = &s_del[row * KN];
            float a = 0.f;
            #pragma unroll
            for (int k = 0; k < KN; k++) {
                float v = cos_cw(__fadd_rn(__fmul_rn(dl[k], wj), bj));
                a = fmaf(mk[k], v, a);
            }
            xs[(2 * D_FEAT + j) * XS_ST + row] = a * inv + cos_cw(bj);
        }
    }
    __syncthreads();

    // ---- phase 2: GEMM; thread = column x all 4 rows ----
    {
        const int col = t;
        ull acc0 = 0ULL, acc1 = 0ULL;   // rows (0,1), (2,3)

        const float* Ws[3]   = { W_node, W_edge, W_time };
        const int    Klen[3] = { D_FEAT, D_FEAT, D_TIME };
        const int    Koff[3] = { 0, D_FEAT, 2 * D_FEAT };

        #pragma unroll
        for (int seg = 0; seg < 3; seg++) {
            const float* Wp = Ws[seg] + col;
            const int kl = Klen[seg];
            const int xo = Koff[seg];
            int kb = 0;
            #pragma unroll 1
            for (; kb + 8 <= kl; kb += 8) {
                float w[8];
                #pragma unroll
                for (int i = 0; i < 8; i++)
                    w[i] = __ldg(Wp + (size_t)(kb + i) * D_EMB);
                #pragma unroll
                for (int i = 0; i < 8; i++) {
                    const ulonglong2 xa = *(const ulonglong2*)&xs[(xo + kb + i) * XS_ST]; // rows 0-3 (LDS.128 bcast)
                    const ull w2 = dup2(w[i]);
                    fma2(acc0, xa.x, w2);
                    fma2(acc1, xa.y, w2);
                }
            }
            // tail (4 for each segment: 172%8=4, 100%8=4)
            #pragma unroll
            for (int i = 0; i < 4; i++) {
                const float wv = __ldg(Wp + (size_t)(kb + i) * D_EMB);
                const ulonglong2 xa = *(const ulonglong2*)&xs[(xo + kb + i) * XS_ST];
                const ull w2 = dup2(wv);
                fma2(acc0, xa.x, w2);
                fma2(acc1, xa.y, w2);
            }
        }

        // ---- epilogue: unpack, add base, store ----
        float v0, v1, v2, v3;
        unpack2(acc0, v0, v1);
        unpack2(acc1, v2, v3);
        out[(size_t)(m0 + 0) * D_EMB + col] = v0 + sbase[0 * D_EMB + col];
        out[(size_t)(m0 + 1) * D_EMB + col] = v1 + sbase[1 * D_EMB + col];
        out[(size_t)(m0 + 2) * D_EMB + col] = v2 + sbase[2 * D_EMB + col];
        out[(size_t)(m0 + 3) * D_EMB + col] = v3 + sbase[3 * D_EMB + col];
    }
}

extern "C" void kernel_launch(void* const* d_in, const int* in_sizes, int n_in,
                              void* d_out, int out_size) {
    const float* node_features = (const float*)d_in[0];
    const float* edge_features = (const float*)d_in[1];
    const float* memory        = (const float*)d_in[2];
    const float* timestamps    = (const float*)d_in[3];
    const float* edge_times    = (const float*)d_in[4];
    const float* time_w        = (const float*)d_in[5];
    const float* time_b        = (const float*)d_in[6];
    const float* W_node        = (const float*)d_in[7];
    const float* W_edge        = (const float*)d_in[8];
    const float* W_time        = (const float*)d_in[9];
    const int*   source_nodes  = (const int*)d_in[10];
    const int*   neighbors     = (const int*)d_in[11];
    const int*   edge_idxs     = (const int*)d_in[12];
    float* out = (float*)d_out;

    fused_kernel<<<BN / GROWS, TPB>>>(node_features, edge_features, memory,
                                      timestamps, edge_times, time_w, time_b,
                                      source_nodes, neighbors, edge_idxs,
                                      W_node, W_edge, W_time, out);
}

// round 16
// speedup vs baseline: 1.0375x; 1.0375x over previous
#include <cuda_runtime.h>
#include <cuda_bf16.h>
#include <cstdint>

// ---------------- problem constants ----------------
#define BN      4096
#define KN      20
#define D_EMB   128
#define D_FEAT  172
#define D_TIME  100
#define KTOT    444              // node 172 | edge 172 | time 100
#define GROWS   8                // batch rows per block
#define XS_ST   12               // xs k-stride: row pairs 8B-aligned
#define TPB     256
#define TASKS_PER_ROW 224        // 43 node-f4 | 43 edge-f4 | 32 mem-f4 | 100 cos | 6 pad
#define NTASKS  (GROWS * TASKS_PER_ROW)   // 1792

typedef unsigned long long ull;

// ---------------- accurate cos for large fp32 args (validated) ----------------
__device__ __forceinline__ float cos_cw(float x) {
    const float TWO_OVER_PI = 0.63661977236758134f;
    const float P1 = 1.57079625129699707031e+00f;
    const float P2 = 7.54978941586159375e-08f;
    const float P3 = 5.39030252995776477e-15f;
    float n = rintf(x * TWO_OVER_PI);
    float r = fmaf(n, -P1, x);
    r = fmaf(n, -P2, r);
    r = fmaf(n, -P3, r);
    int q = ((int)n) & 3;
    float r2 = r * r;
    float s = fmaf(r2, -1.98412698412698413e-4f, 8.33333333333333322e-3f);
    s = fmaf(r2, s, -1.66666666666666666e-1f);
    s = r * fmaf(r2, s, 1.0f);
    float c = fmaf(r2, 2.48015873015873016e-5f, -1.38888888888888889e-3f);
    c = fmaf(r2, c, 4.16666666666666666e-2f);
    c = fmaf(r2, c, -0.5f);
    c = fmaf(r2, c, 1.0f);
    float v = (q & 1) ? s : c;
    if ((q + 1) & 2) v = -v;
    return v;
}

// ---------------- f32x2 packed helpers ----------------
__device__ __forceinline__ ull dup2(float v) {
    ull r;
    asm("mov.b64 %0, {%1, %1};" : "=l"(r) : "f"(v));
    return r;
}
__device__ __forceinline__ void fma2(ull& d, ull a, ull b) {
    asm("fma.rn.f32x2 %0, %1, %2, %0;" : "+l"(d) : "l"(a), "l"(b));
}
__device__ __forceinline__ void unpack2(ull v, float& lo, float& hi) {
    asm("mov.b64 {%0, %1}, %2;" : "=f"(lo), "=f"(hi) : "l"(v));
}
// asm-pinned vector gather: ptxas cannot sink/shrink this — forces the MLP window.
__device__ __forceinline__ float4 ldg_v4_pin(const float* p) {
    float4 v;
    asm volatile("ld.global.nc.v4.f32 {%0, %1, %2, %3}, [%4];"
                 : "=f"(v.x), "=f"(v.y), "=f"(v.z), "=f"(v.w) : "l"(p));
    return v;
}

// ---------------- fused gather + masked-mean + projection GEMM ----------------
// Block = 8 batch rows, 256 threads. Phase 1: task-based float4 gather-reduce with
// asm-pinned MLP-10 load batches. Phase 2: lane-per-column f32x2 GEMM (validated).
__global__ void __launch_bounds__(TPB) fused_kernel(
    const float* __restrict__ nf, const float* __restrict__ ef,
    const float* __restrict__ mem,
    const float* __restrict__ ts, const float* __restrict__ ets,
    const float* __restrict__ tw, const float* __restrict__ tb,
    const int* __restrict__ srcn, const int* __restrict__ nbr,
    const int* __restrict__ eidx,
    const float* __restrict__ W_node, const float* __restrict__ W_edge,
    const float* __restrict__ W_time,
    float* __restrict__ out)
{
    __shared__ __align__(16) float xs[KTOT * XS_ST];   // 21312 B transposed X tile
    __shared__ float sbase[GROWS * D_EMB];             // 4096 B memory terms
    __shared__ int   s_nbr[GROWS * KN];
    __shared__ int   s_eid[GROWS * KN];
    __shared__ float s_del[GROWS * KN];
    __shared__ float s_msk[GROWS * KN];
    __shared__ float s_inv[GROWS];
    __shared__ int   s_src[GROWS];

    const int t = threadIdx.x;
    const int m0 = blockIdx.x * GROWS;

    // ---- phase 0: metadata ----
    if (t < GROWS * KN) {
        const int row = t / KN;
        const int kk = t - row * KN;
        const int gb = m0 + row;
        const int nb = __ldg(&nbr[gb * KN + kk]);
        s_nbr[t] = nb;
        s_eid[t] = __ldg(&eidx[gb * KN + kk]);
        s_del[t] = __ldg(&ts[gb]) - __ldg(&ets[gb * KN + kk]);
        s_msk[t] = (nb != 0) ? 1.f : 0.f;
    }
    if (t >= 224 && t < 224 + GROWS) s_src[t - 224] = __ldg(&srcn[m0 + (t - 224)]);
    __syncthreads();
    if (t < GROWS) {
        float c = 0.f;
        #pragma unroll
        for (int k = 0; k < KN; k++) c += s_msk[t * KN + k];
        s_inv[t] = 1.f / fmaxf(c, 1.f);
    }
    __syncthreads();

    // ---- phase 1: task loop with asm-pinned MLP-10 gather batches ----
    for (int ti = t; ti < NTASKS; ti += TPB) {
        const int row = ti / TASKS_PER_ROW;
        const int tt = ti - row * TASKS_PER_ROW;
        const float inv = s_inv[row];
        const float* mk = &s_msk[row * KN];

        if (tt < 118) {
            const float* bp;
            int stride, colo, xoff;
            const int* rs;
            bool add_src, to_base = false;
            if (tt < 43)      { bp = nf;  stride = D_FEAT; colo = 4 * tt;        rs = &s_nbr[row * KN]; xoff = 0;      add_src = true; }
            else if (tt < 86) { bp = ef;  stride = D_FEAT; colo = 4 * (tt - 43); rs = &s_eid[row * KN]; xoff = D_FEAT; add_src = false; }
            else              { bp = mem; stride = D_EMB;  colo = 4 * (tt - 86); rs = &s_nbr[row * KN]; xoff = 0;      add_src = true; to_base = true; }

            float4 acc = make_float4(0.f, 0.f, 0.f, 0.f);
            float4 v[10];
            // batch 1: k = 0..9 — 10 LDG.128 pinned in flight before any FMA
            #pragma unroll
            for (int k = 0; k < 10; k++)
                v[k] = ldg_v4_pin(bp + (size_t)rs[k] * stride + colo);
            #pragma unroll
            for (int k = 0; k < 10; k++) {
                const float m = mk[k];
                acc.x = fmaf(m, v[k].x, acc.x);
                acc.y = fmaf(m, v[k].y, acc.y);
                acc.z = fmaf(m, v[k].z, acc.z);
                acc.w = fmaf(m, v[k].w, acc.w);
            }
            // batch 2: k = 10..19
            #pragma unroll
            for (int k = 0; k < 10; k++)
                v[k] = ldg_v4_pin(bp + (size_t)rs[k + 10] * stride + colo);
            #pragma unroll
            for (int k = 0; k < 10; k++) {
                const float m = mk[k + 10];
                acc.x = fmaf(m, v[k].x, acc.x);
                acc.y = fmaf(m, v[k].y, acc.y);
                acc.z = fmaf(m, v[k].z, acc.z);
                acc.w = fmaf(m, v[k].w, acc.w);
            }
            acc.x *= inv; acc.y *= inv; acc.z *= inv; acc.w *= inv;
            if (add_src) {
                const float4 sv = __ldg((const float4*)(bp + (size_t)s_src[row] * stride + colo));
                acc.x += sv.x; acc.y += sv.y; acc.z += sv.z; acc.w += sv.w;
            }
            if (to_base) {
                *(float4*)&sbase[row * D_EMB + colo] = acc;
            } else {
                const int c = xoff + colo;
                xs[(c + 0) * XS_ST + row] = acc.x;
                xs[(c + 1) * XS_ST + row] = acc.y;
                xs[(c + 2) * XS_ST + row] = acc.z;
                xs[(c + 3) * XS_ST + row] = acc.w;
            }
        } else if (tt < 218) {
            const int j = tt - 118;
            const float wj = __ldg(&tw[j]);
            const float bj = __ldg(&tb[j]);
            const float* dl = &s_del[row * KN];
            float a = 0.f;
            #pragma unroll
            for (int k = 0; k < KN; k++) {
                float v = cos_cw(__fadd_rn(__fmul_rn(dl[k], wj), bj));
                a = fmaf(mk[k], v, a);
            }
            xs[(2 * D_FEAT + j) * XS_ST + row] = a * inv + cos_cw(bj);
        }
    }
    __syncthreads();

    // ---- phase 2: GEMM (validated). col = t&127; rows r0 = 4*(t>>7) .. r0+3 ----
    const int col = t & 127;
    const int r0 = (t >> 7) * 4;

    ull acc0 = 0ULL, acc1 = 0ULL;   // rows (r0,r0+1), (r0+2,r0+3)

    const float* Ws[3]   = { W_node, W_edge, W_time };
    const int    Klen[3] = { D_FEAT, D_FEAT, D_TIME };
    const int    Koff[3] = { 0, D_FEAT, 2 * D_FEAT };

    #pragma unroll
    for (int seg = 0; seg < 3; seg++) {
        const float* Wp = Ws[seg] + col;
        const int kl = Klen[seg];
        const int xo = Koff[seg];
        int kb = 0;
        #pragma unroll 1
        for (; kb + 8 <= kl; kb += 8) {
            float w[8];
            #pragma unroll
            for (int i = 0; i < 8; i++)
                w[i] = __ldg(Wp + (size_t)(kb + i) * D_EMB);
            #pragma unroll
            for (int i = 0; i < 8; i++) {
                const float* xk = &xs[(xo + kb + i) * XS_ST + r0];
                ull xA = *(const ull*)xk;         // broadcast LDS.64
                ull xB = *(const ull*)(xk + 2);   // broadcast LDS.64
                const ull w2 = dup2(w[i]);
                fma2(acc0, xA, w2);
                fma2(acc1, xB, w2);
            }
        }
        // tail (4 for each segment: 172%8=4, 100%8=4)
        #pragma unroll
        for (int i = 0; i < 4; i++) {
            const float wv = __ldg(Wp + (size_t)(kb + i) * D_EMB);
            const float* xk = &xs[(xo + kb + i) * XS_ST + r0];
            ull xA = *(const ull*)xk;
            ull xB = *(const ull*)(xk + 2);
            const ull w2 = dup2(wv);
            fma2(acc0, xA, w2);
            fma2(acc1, xB, w2);
        }
    }

    // ---- epilogue ----
    float v0, v1, v2, v3;
    unpack2(acc0, v0, v1);
    unpack2(acc1, v2, v3);
    out[(size_t)(m0 + r0 + 0) * D_EMB + col] = v0 + sbase[(r0 + 0) * D_EMB + col];
    out[(size_t)(m0 + r0 + 1) * D_EMB + col] = v1 + sbase[(r0 + 1) * D_EMB + col];
    out[(size_t)(m0 + r0 + 2) * D_EMB + col] = v2 + sbase[(r0 + 2) * D_EMB + col];
    out[(size_t)(m0 + r0 + 3) * D_EMB + col] = v3 + sbase[(r0 + 3) * D_EMB + col];
}

extern "C" void kernel_launch(void* const* d_in, const int* in_sizes, int n_in,
                              void* d_out, int out_size) {
    const float* node_features = (const float*)d_in[0];
    const float* edge_features = (const float*)d_in[1];
    const float* memory        = (const float*)d_in[2];
    const float* timestamps    = (const float*)d_in[3];
    const float* edge_times    = (const float*)d_in[4];
    const float* time_w        = (const float*)d_in[5];
    const float* time_b        = (const float*)d_in[6];
    const float* W_node        = (const float*)d_in[7];
    const float* W_edge        = (const float*)d_in[8];
    const float* W_time        = (const float*)d_in[9];
    const int*   source_nodes  = (const int*)d_in[10];
    const int*   neighbors     = (const int*)d_in[11];
    const int*   edge_idxs     = (const int*)d_in[12];
    float* out = (float*)d_out;

    fused_kernel<<<BN / GROWS, TPB>>>(node_features, edge_features, memory,
                                      timestamps, edge_times, time_w, time_b,
                                      source_nodes, neighbors, edge_idxs,
                                      W_node, W_edge, W_time, out);
}